// round 6
// baseline (speedup 1.0000x reference)
#include <cuda_runtime.h>
#include <math.h>

// Problem constants
#define BB 64
#define TT 512
#define II 1024
#define HH 1024

#define NB_CTAS 128
#define RNN_THREADS 256

// ---------------- device scratch ----------------
__device__ float g_h[2][BB * HH];                       // ping-pong hidden state
__device__ __align__(512) unsigned g_flags[4][32];      // per-bt-group step flags

// ---------------- helpers ----------------
__device__ __forceinline__ unsigned f2tf32(float x) {
    unsigned r;
    asm("cvt.rna.tf32.f32 %0, %1;" : "=r"(r) : "f"(x));
    return r;
}

__device__ __forceinline__ void ldmat_x4(unsigned* r, unsigned addr) {
    asm volatile("ldmatrix.sync.aligned.m8n8.x4.shared.b16 {%0,%1,%2,%3}, [%4];"
                 : "=r"(r[0]), "=r"(r[1]), "=r"(r[2]), "=r"(r[3]) : "r"(addr));
}

__device__ __forceinline__ void mma_tf32(float* c, const unsigned* a, unsigned b0, unsigned b1) {
    asm volatile(
        "mma.sync.aligned.m16n8k8.row.col.f32.tf32.tf32.f32 "
        "{%0,%1,%2,%3},{%4,%5,%6,%7},{%8,%9},{%0,%1,%2,%3};"
        : "+f"(c[0]), "+f"(c[1]), "+f"(c[2]), "+f"(c[3])
        : "r"(a[0]), "r"(a[1]), "r"(a[2]), "r"(a[3]), "r"(b0), "r"(b1));
}

// ---------------- init ----------------
__global__ void init_kernel(const float* __restrict__ h0) {
    int i = blockIdx.x * blockDim.x + threadIdx.x;
    if (i < BB * HH) g_h[0][i] = h0[i];
    if (i < 128) ((unsigned*)g_flags)[i] = 0u;
}

// ---------------- phase 1: xp = x @ W_ih^T + b_ih  (tf32 mma) -------------
// CTA tile 128(M) x 128(N), k-chunk 32. 8 warps (2m x 4n), warp tile 64x32.
__global__ void __launch_bounds__(256) gemm_xw_mma(
    const float* __restrict__ A,    // x [M][K]
    const float* __restrict__ W,    // W_ih [N][K]
    const float* __restrict__ bias, // [N]
    float* __restrict__ C)          // [M][N]
{
    __shared__ unsigned As[128 * 32];
    __shared__ unsigned Ws[128 * 32];

    const int tid  = threadIdx.x;
    const int lane = tid & 31;
    const int warp = tid >> 5;
    const int wm   = warp & 1;   // 0..1
    const int wn   = warp >> 1;  // 0..3
    const int n0   = blockIdx.x * 128;
    const int m0   = blockIdx.y * 128;

    const unsigned AsB = (unsigned)__cvta_generic_to_shared(As);
    const unsigned WsB = (unsigned)__cvta_generic_to_shared(Ws);

    float c[4][4][4] = {};

    int lr[4], lg[4];
    size_t aoff[4], woff[4];
#pragma unroll
    for (int i = 0; i < 4; i++) {
        int idx = tid + i * 256;
        lr[i] = idx >> 3;
        lg[i] = idx & 7;
        aoff[i] = (size_t)(m0 + lr[i]) * II + lg[i] * 4;
        woff[i] = (size_t)(n0 + lr[i]) * II + lg[i] * 4;
    }

    float4 ra[4], rw[4];
#pragma unroll
    for (int i = 0; i < 4; i++) {
        ra[i] = *(const float4*)(A + aoff[i]);
        rw[i] = *(const float4*)(W + woff[i]);
    }

    for (int kc = 0; kc < 32; kc++) {
        __syncthreads();
#pragma unroll
        for (int i = 0; i < 4; i++) {
            uint4 ua = { f2tf32(ra[i].x), f2tf32(ra[i].y), f2tf32(ra[i].z), f2tf32(ra[i].w) };
            uint4 uw = { f2tf32(rw[i].x), f2tf32(rw[i].y), f2tf32(rw[i].z), f2tf32(rw[i].w) };
            int off = lr[i] * 32 + ((lg[i] ^ (lr[i] & 7)) << 2);
            *(uint4*)&As[off] = ua;
            *(uint4*)&Ws[off] = uw;
        }
        __syncthreads();

        if (kc + 1 < 32) {
            int k0 = (kc + 1) * 32;
#pragma unroll
            for (int i = 0; i < 4; i++) {
                ra[i] = *(const float4*)(A + aoff[i] + k0);
                rw[i] = *(const float4*)(W + woff[i] + k0);
            }
        }

#pragma unroll
        for (int ks = 0; ks < 4; ks++) {
            unsigned a[4][4], b[4][2];
#pragma unroll
            for (int mi = 0; mi < 4; mi++) {
                int r = wm * 64 + mi * 16 + ((lane >> 3) & 1) * 8 + (lane & 7);
                int g = ks * 2 + (lane >> 4);
                ldmat_x4(a[mi], AsB + (unsigned)(r * 32 + ((g ^ (r & 7)) << 2)) * 4u);
            }
#pragma unroll
            for (int p = 0; p < 2; p++) {
                int r = wn * 32 + p * 16 + (lane >> 4) * 8 + (lane & 7);
                int g = ks * 2 + ((lane >> 3) & 1);
                unsigned t[4];
                ldmat_x4(t, WsB + (unsigned)(r * 32 + ((g ^ (r & 7)) << 2)) * 4u);
                b[p * 2 + 0][0] = t[0]; b[p * 2 + 0][1] = t[1];
                b[p * 2 + 1][0] = t[2]; b[p * 2 + 1][1] = t[3];
            }
#pragma unroll
            for (int mi = 0; mi < 4; mi++)
#pragma unroll
                for (int ni = 0; ni < 4; ni++)
                    mma_tf32(c[mi][ni], a[mi], b[ni][0], b[ni][1]);
        }
    }

#pragma unroll
    for (int mi = 0; mi < 4; mi++) {
        int r = m0 + wm * 64 + mi * 16 + (lane >> 2);
#pragma unroll
        for (int ni = 0; ni < 4; ni++) {
            int col = n0 + wn * 32 + ni * 8 + (lane & 3) * 2;
            float2 bv = *(const float2*)&bias[col];
            float2 o0 = { c[mi][ni][0] + bv.x, c[mi][ni][1] + bv.y };
            float2 o1 = { c[mi][ni][2] + bv.x, c[mi][ni][3] + bv.y };
            *(float2*)&C[(size_t)r * HH + col]       = o0;
            *(float2*)&C[(size_t)(r + 8) * HH + col] = o1;
        }
    }
}

// ---------------- phase 2: persistent recurrent scan (tf32 mma) ----------
// 128 CTAs = 32 H-tiles (32 cols) x 4 B-tiles (16 rows). W_hh slice resident
// in smem. 8 warps = 2 n-halves x 4-way split-K. Per-bt-group flag barrier.
__global__ void __launch_bounds__(RNN_THREADS, 1) rnn_scan_mma(
    const float* __restrict__ W_hh,
    const float* __restrict__ b_hh,
    float* __restrict__ out)
{
    extern __shared__ unsigned smbuf[];
    unsigned* Wt = smbuf;             // [32][1024] tf32 swizzled (n-major)
    unsigned* Ht = smbuf + 32 * 1024; // [16][1024] tf32 swizzled
    float* red = (float*)(smbuf + 48 * 1024); // [4][16*33] split-K partials

    const int tid  = threadIdx.x;
    const int lane = tid & 31;
    const int warp = tid >> 5;
    const int nf2  = warp & 1;   // n half: cols 0-15 / 16-31
    const int kq   = warp >> 1;  // k quarter: 256 k each
    const int bid  = blockIdx.x;
    const int ht   = bid & 31;
    const int bt   = bid >> 5;

    const unsigned HtB = (unsigned)__cvta_generic_to_shared(Ht);
    const unsigned WtB = (unsigned)__cvta_generic_to_shared(Wt);

    // ---- load W_hh slice: rows = i, granule = tid ----
#pragma unroll
    for (int i = 0; i < 32; i++) {
        float4 v = *(const float4*)(W_hh + (((size_t)(ht * 32 + i)) << 10) + tid * 4);
        uint4 u = { f2tf32(v.x), f2tf32(v.y), f2tf32(v.z), f2tf32(v.w) };
        *(uint4*)&Wt[i * 1024 + ((tid ^ (i & 7)) << 2)] = u;
    }

    // ---- mma fragment constants ----
    const int rowb = lane >> 2;                 // 0..7
    const int colb = nf2 * 16 + 2 * (lane & 3); // even col within tile
    const int kg0  = kq << 6;                   // granule base of k quarter

    // ---- per-thread epilogue constants (each thread owns 2 adjacent outs) ----
    const int erow = tid >> 4;          // 0..15
    const int ecol = (2 * tid) & 31;    // even
    const int gb   = bt * 16 + erow;
    const int gc   = ht * 32 + ecol;
    const float2 bh = *(const float2*)&b_hh[gc];
    float* oPtr = out + (size_t)gb * TT * HH + gc;
    float* hOutBase0 = &g_h[1][(size_t)gb * HH + gc];  // buffer written at even t
    float* hOutBase1 = &g_h[0][(size_t)gb * HH + gc];  // buffer written at odd t
    volatile unsigned* myFlag  = &g_flags[bt][ht];
    volatile unsigned* grpFlag = &g_flags[bt][lane];

    for (int t = 0; t < TT; ++t) {
        const int cur = t & 1;
        const float* hsrc = &g_h[cur][(size_t)bt * 16 * HH];

        // ---- xp prefetch (independent of h; hides DRAM latency) ----
        float2 xp = __ldcg((const float2*)(oPtr + (size_t)t * HH));

        // ---- group barrier: wait until all 32 same-bt CTAs finished step t-1
        if (t > 0) {
            if (warp == 0) {
                while (true) {
                    unsigned v = *grpFlag;
                    if (__all_sync(0xffffffffu, v >= (unsigned)t)) break;
                }
            }
            __syncthreads();
            __threadfence();
        }

        // ---- stage h_{t-1} tile into smem as tf32 swizzled ----
#pragma unroll
        for (int i = 0; i < 16; i++) {
            float4 v = __ldcg((const float4*)(hsrc + ((size_t)i << 10) + tid * 4));
            uint4 u = { f2tf32(v.x), f2tf32(v.y), f2tf32(v.z), f2tf32(v.w) };
            *(uint4*)&Ht[i * 1024 + ((tid ^ (i & 7)) << 2)] = u;
        }
        __syncthreads();

        // ---- mma over this warp's 256-k quarter, 2 n-frags ----
        float c[2][2][4] = {};
#pragma unroll 4
        for (int s2 = 0; s2 < 16; s2++) {
            int g0 = kg0 + s2 * 4;
            unsigned a0[4], a1[4], b0[4], b1[4];
            {
                int r = (lane & 7) + ((lane >> 3) & 1) * 8;
                int g = g0 + (lane >> 4);
                ldmat_x4(a0, HtB + (unsigned)(r * 1024 + ((g ^ (r & 7)) << 2)) * 4u);
                g += 2;
                ldmat_x4(a1, HtB + (unsigned)(r * 1024 + ((g ^ (r & 7)) << 2)) * 4u);
            }
            {
                int r = nf2 * 16 + (lane & 7);
                int g = g0 + (lane >> 3);
                ldmat_x4(b0, WtB + (unsigned)(r * 1024 + ((g ^ (r & 7)) << 2)) * 4u);
                int r2 = r + 8;
                ldmat_x4(b1, WtB + (unsigned)(r2 * 1024 + ((g ^ (r2 & 7)) << 2)) * 4u);
            }
            mma_tf32(c[0][0], a0, b0[0], b0[1]);
            mma_tf32(c[0][1], a0, b1[0], b1[1]);
            mma_tf32(c[1][0], a1, b0[2], b0[3]);
            mma_tf32(c[1][1], a1, b1[2], b1[3]);
        }

        // ---- every warp dumps partials; all 256 threads reduce ----
#pragma unroll
        for (int ni = 0; ni < 2; ni++) {
#pragma unroll
            for (int half = 0; half < 2; half++) {
                int r = rowb + 8 * half;
                int cc = colb + ni * 8;
                red[kq * 528 + r * 33 + cc]     = c[0][ni][half * 2]     + c[1][ni][half * 2];
                red[kq * 528 + r * 33 + cc + 1] = c[0][ni][half * 2 + 1] + c[1][ni][half * 2 + 1];
            }
        }
        __syncthreads();

        float s0 = xp.x + bh.x;
        float s1 = xp.y + bh.y;
#pragma unroll
        for (int q = 0; q < 4; q++) {
            s0 += red[q * 528 + erow * 33 + ecol];
            s1 += red[q * 528 + erow * 33 + ecol + 1];
        }
        float2 hv = { tanhf(s0), tanhf(s1) };

        *(float2*)(oPtr + (size_t)t * HH) = hv;
        __stcg((float2*)(cur ? hOutBase1 : hOutBase0), hv);

        // ---- arrival: all stores visible, then bump own flag ----
        __threadfence();
        __syncthreads();
        if (tid == 0) *myFlag = (unsigned)(t + 1);
    }
}

// ---------------- launch ----------------
extern "C" void kernel_launch(void* const* d_in, const int* in_sizes, int n_in,
                              void* d_out, int out_size) {
    const float* x    = (const float*)d_in[0];
    const float* h0   = (const float*)d_in[1];
    const float* W_ih = (const float*)d_in[2];
    const float* b_ih = (const float*)d_in[3];
    const float* W_hh = (const float*)d_in[4];
    const float* b_hh = (const float*)d_in[5];
    float* out = (float*)d_out;

    init_kernel<<<(BB * HH + 255) / 256, 256>>>(h0);

    dim3 g1(HH / 128, (BB * TT) / 128);
    gemm_xw_mma<<<g1, 256>>>(x, W_ih, b_ih, out);

    const int smem_bytes = (48 * 1024) * 4 + 4 * 528 * 4;  // 205056 B
    cudaFuncSetAttribute(rnn_scan_mma,
                         cudaFuncAttributeMaxDynamicSharedMemorySize, smem_bytes);
    rnn_scan_mma<<<NB_CTAS, RNN_THREADS, smem_bytes>>>(W_hh, b_hh, out);
}

// round 8
// speedup vs baseline: 1.7287x; 1.7287x over previous
#include <cuda_runtime.h>
#include <math.h>

// Problem constants
#define BB 64
#define TT 512
#define II 1024
#define HH 1024

#define NB_CTAS 128
#define RNN_THREADS 256

// ---------------- device scratch ----------------
__device__ float g_h[2][BB * HH];                     // ping-pong hidden state
__device__ __align__(512) unsigned g_cnt[4 * 32];     // per-bt-group counters (128B apart)

// ---------------- helpers ----------------
__device__ __forceinline__ unsigned f2tf32(float x) {
    unsigned r;
    asm("cvt.rna.tf32.f32 %0, %1;" : "=r"(r) : "f"(x));
    return r;
}

__device__ __forceinline__ void ldmat_x4(unsigned* r, unsigned addr) {
    asm volatile("ldmatrix.sync.aligned.m8n8.x4.shared.b16 {%0,%1,%2,%3}, [%4];"
                 : "=r"(r[0]), "=r"(r[1]), "=r"(r[2]), "=r"(r[3]) : "r"(addr));
}

__device__ __forceinline__ void mma_tf32(float* c, const unsigned* a, unsigned b0, unsigned b1) {
    asm volatile(
        "mma.sync.aligned.m16n8k8.row.col.f32.tf32.tf32.f32 "
        "{%0,%1,%2,%3},{%4,%5,%6,%7},{%8,%9},{%0,%1,%2,%3};"
        : "+f"(c[0]), "+f"(c[1]), "+f"(c[2]), "+f"(c[3])
        : "r"(a[0]), "r"(a[1]), "r"(a[2]), "r"(a[3]), "r"(b0), "r"(b1));
}

// ---------------- init ----------------
__global__ void init_kernel(const float* __restrict__ h0) {
    int i = blockIdx.x * blockDim.x + threadIdx.x;
    if (i < BB * HH) g_h[0][i] = h0[i];
    if (i < 128) g_cnt[i] = 0u;
}

// ---------------- phase 1: xp = x @ W_ih^T + b_ih  (tf32 mma) -------------
// CTA tile 128(M) x 128(N), k-chunk 32. 8 warps (2m x 4n), warp tile 64x32.
__global__ void __launch_bounds__(256) gemm_xw_mma(
    const float* __restrict__ A,    // x [M][K]
    const float* __restrict__ W,    // W_ih [N][K]
    const float* __restrict__ bias, // [N]
    float* __restrict__ C)          // [M][N]
{
    __shared__ unsigned As[128 * 32];
    __shared__ unsigned Ws[128 * 32];

    const int tid  = threadIdx.x;
    const int lane = tid & 31;
    const int warp = tid >> 5;
    const int wm   = warp & 1;   // 0..1
    const int wn   = warp >> 1;  // 0..3
    const int n0   = blockIdx.x * 128;
    const int m0   = blockIdx.y * 128;

    const unsigned AsB = (unsigned)__cvta_generic_to_shared(As);
    const unsigned WsB = (unsigned)__cvta_generic_to_shared(Ws);

    float c[4][4][4] = {};

    int lr[4], lg[4];
    size_t aoff[4], woff[4];
#pragma unroll
    for (int i = 0; i < 4; i++) {
        int idx = tid + i * 256;
        lr[i] = idx >> 3;
        lg[i] = idx & 7;
        aoff[i] = (size_t)(m0 + lr[i]) * II + lg[i] * 4;
        woff[i] = (size_t)(n0 + lr[i]) * II + lg[i] * 4;
    }

    float4 ra[4], rw[4];
#pragma unroll
    for (int i = 0; i < 4; i++) {
        ra[i] = *(const float4*)(A + aoff[i]);
        rw[i] = *(const float4*)(W + woff[i]);
    }

    for (int kc = 0; kc < 32; kc++) {
        __syncthreads();
#pragma unroll
        for (int i = 0; i < 4; i++) {
            uint4 ua = { f2tf32(ra[i].x), f2tf32(ra[i].y), f2tf32(ra[i].z), f2tf32(ra[i].w) };
            uint4 uw = { f2tf32(rw[i].x), f2tf32(rw[i].y), f2tf32(rw[i].z), f2tf32(rw[i].w) };
            int off = lr[i] * 32 + ((lg[i] ^ (lr[i] & 7)) << 2);
            *(uint4*)&As[off] = ua;
            *(uint4*)&Ws[off] = uw;
        }
        __syncthreads();

        if (kc + 1 < 32) {
            int k0 = (kc + 1) * 32;
#pragma unroll
            for (int i = 0; i < 4; i++) {
                ra[i] = *(const float4*)(A + aoff[i] + k0);
                rw[i] = *(const float4*)(W + woff[i] + k0);
            }
        }

#pragma unroll
        for (int ks = 0; ks < 4; ks++) {
            unsigned a[4][4], b[4][2];
#pragma unroll
            for (int mi = 0; mi < 4; mi++) {
                int r = wm * 64 + mi * 16 + ((lane >> 3) & 1) * 8 + (lane & 7);
                int g = ks * 2 + (lane >> 4);
                ldmat_x4(a[mi], AsB + (unsigned)(r * 32 + ((g ^ (r & 7)) << 2)) * 4u);
            }
#pragma unroll
            for (int p = 0; p < 2; p++) {
                int r = wn * 32 + p * 16 + (lane >> 4) * 8 + (lane & 7);
                int g = ks * 2 + ((lane >> 3) & 1);
                unsigned t[4];
                ldmat_x4(t, WsB + (unsigned)(r * 32 + ((g ^ (r & 7)) << 2)) * 4u);
                b[p * 2 + 0][0] = t[0]; b[p * 2 + 0][1] = t[1];
                b[p * 2 + 1][0] = t[2]; b[p * 2 + 1][1] = t[3];
            }
#pragma unroll
            for (int mi = 0; mi < 4; mi++)
#pragma unroll
                for (int ni = 0; ni < 4; ni++)
                    mma_tf32(c[mi][ni], a[mi], b[ni][0], b[ni][1]);
        }
    }

#pragma unroll
    for (int mi = 0; mi < 4; mi++) {
        int r = m0 + wm * 64 + mi * 16 + (lane >> 2);
#pragma unroll
        for (int ni = 0; ni < 4; ni++) {
            int col = n0 + wn * 32 + ni * 8 + (lane & 3) * 2;
            float2 bv = *(const float2*)&bias[col];
            float2 o0 = { c[mi][ni][0] + bv.x, c[mi][ni][1] + bv.y };
            float2 o1 = { c[mi][ni][2] + bv.x, c[mi][ni][3] + bv.y };
            *(float2*)&C[(size_t)r * HH + col]       = o0;
            *(float2*)&C[(size_t)(r + 8) * HH + col] = o1;
        }
    }
}

// ---------------- phase 2: persistent recurrent scan (tf32 mma) ----------
// 128 CTAs = 32 H-tiles (32 cols) x 4 B-tiles (16 rows). W_hh slice resident
// in smem. 8 warps = 2 n-halves x 4-way split-K.
// Sync: per-bt-group atomic counter, release/acquire, single-thread poll.
__global__ void __launch_bounds__(RNN_THREADS, 1) rnn_scan_mma(
    const float* __restrict__ W_hh,
    const float* __restrict__ b_hh,
    float* __restrict__ out)
{
    extern __shared__ unsigned smbuf[];
    unsigned* Wt = smbuf;             // [32][1024] tf32 swizzled (n-major)
    unsigned* Ht = smbuf + 32 * 1024; // [16][1024] tf32 swizzled
    float* red = (float*)(smbuf + 48 * 1024); // [4][16*33] split-K partials

    const int tid  = threadIdx.x;
    const int lane = tid & 31;
    const int warp = tid >> 5;
    const int nf2  = warp & 1;   // n half: cols 0-15 / 16-31
    const int kq   = warp >> 1;  // k quarter: 256 k each
    const int bid  = blockIdx.x;
    const int ht   = bid & 31;
    const int bt   = bid >> 5;

    const unsigned HtB = (unsigned)__cvta_generic_to_shared(Ht);
    const unsigned WtB = (unsigned)__cvta_generic_to_shared(Wt);

    // ---- load W_hh slice ----
#pragma unroll
    for (int i = 0; i < 32; i++) {
        float4 v = *(const float4*)(W_hh + (((size_t)(ht * 32 + i)) << 10) + tid * 4);
        uint4 u = { f2tf32(v.x), f2tf32(v.y), f2tf32(v.z), f2tf32(v.w) };
        *(uint4*)&Wt[i * 1024 + ((tid ^ (i & 7)) << 2)] = u;
    }

    // ---- mma fragment constants ----
    const int rowb = lane >> 2;
    const int colb = nf2 * 16 + 2 * (lane & 3);
    const int kg0  = kq << 6;

    // ---- per-thread epilogue constants (2 adjacent outputs/thread) ----
    const int erow = tid >> 4;
    const int ecol = (2 * tid) & 31;
    const int gb   = bt * 16 + erow;
    const int gc   = ht * 32 + ecol;
    const float2 bh = *(const float2*)&b_hh[gc];
    float* oPtr = out + (size_t)gb * TT * HH + gc;
    float* hOutBase0 = &g_h[1][(size_t)gb * HH + gc];  // written at even t
    float* hOutBase1 = &g_h[0][(size_t)gb * HH + gc];  // written at odd t
    unsigned* cnt = &g_cnt[bt * 32];

    for (int t = 0; t < TT; ++t) {
        const int cur = t & 1;
        const float* hsrc = &g_h[cur][(size_t)bt * 16 * HH];

        // ---- xp prefetch (independent of h; hides DRAM under the wait) ----
        float2 xp = __ldcg((const float2*)(oPtr + (size_t)t * HH));

        // ---- group barrier: single-thread acquire poll on group counter ----
        if (t > 0) {
            if (tid == 0) {
                const unsigned target = 32u * (unsigned)t;
                unsigned v;
                do {
                    asm volatile("ld.acquire.gpu.global.u32 %0, [%1];"
                                 : "=r"(v) : "l"(cnt));
                } while (v < target);
            }
            __syncthreads();
        }

        // ---- stage h_{t-1} tile into smem as tf32 swizzled ----
#pragma unroll
        for (int i = 0; i < 16; i++) {
            float4 v = __ldcg((const float4*)(hsrc + ((size_t)i << 10) + tid * 4));
            uint4 u = { f2tf32(v.x), f2tf32(v.y), f2tf32(v.z), f2tf32(v.w) };
            *(uint4*)&Ht[i * 1024 + ((tid ^ (i & 7)) << 2)] = u;
        }
        __syncthreads();

        // ---- mma over this warp's 256-k quarter, 2 n-frags ----
        float c[2][2][4] = {};
#pragma unroll 4
        for (int s2 = 0; s2 < 16; s2++) {
            int g0 = kg0 + s2 * 4;
            unsigned a0[4], a1[4], b0[4], b1[4];
            {
                int r = (lane & 7) + ((lane >> 3) & 1) * 8;
                int g = g0 + (lane >> 4);
                ldmat_x4(a0, HtB + (unsigned)(r * 1024 + ((g ^ (r & 7)) << 2)) * 4u);
                g += 2;
                ldmat_x4(a1, HtB + (unsigned)(r * 1024 + ((g ^ (r & 7)) << 2)) * 4u);
            }
            {
                int r = nf2 * 16 + (lane & 7);
                int g = g0 + (lane >> 3);
                ldmat_x4(b0, WtB + (unsigned)(r * 1024 + ((g ^ (r & 7)) << 2)) * 4u);
                int r2 = r + 8;
                ldmat_x4(b1, WtB + (unsigned)(r2 * 1024 + ((g ^ (r2 & 7)) << 2)) * 4u);
            }
            mma_tf32(c[0][0], a0, b0[0], b0[1]);
            mma_tf32(c[0][1], a0, b1[0], b1[1]);
            mma_tf32(c[1][0], a1, b0[2], b0[3]);
            mma_tf32(c[1][1], a1, b1[2], b1[3]);
        }

        // ---- every warp dumps partials; all 256 threads reduce ----
#pragma unroll
        for (int ni = 0; ni < 2; ni++) {
#pragma unroll
            for (int half = 0; half < 2; half++) {
                int r = rowb + 8 * half;
                int cc = colb + ni * 8;
                red[kq * 528 + r * 33 + cc]     = c[0][ni][half * 2]     + c[1][ni][half * 2];
                red[kq * 528 + r * 33 + cc + 1] = c[0][ni][half * 2 + 1] + c[1][ni][half * 2 + 1];
            }
        }
        __syncthreads();

        float s0 = xp.x + bh.x;
        float s1 = xp.y + bh.y;
#pragma unroll
        for (int q = 0; q < 4; q++) {
            s0 += red[q * 528 + erow * 33 + ecol];
            s1 += red[q * 528 + erow * 33 + ecol + 1];
        }
        float2 hv = { tanhf(s0), tanhf(s1) };

        *(float2*)(oPtr + (size_t)t * HH) = hv;
        __stcg((float2*)(cur ? hOutBase1 : hOutBase0), hv);

        // ---- arrival: release-add on group counter after CTA-wide drain ----
        __syncthreads();
        if (tid == 0)
            asm volatile("red.release.gpu.global.add.u32 [%0], 1;" :: "l"(cnt));
    }
}

// ---------------- launch ----------------
extern "C" void kernel_launch(void* const* d_in, const int* in_sizes, int n_in,
                              void* d_out, int out_size) {
    const float* x    = (const float*)d_in[0];
    const float* h0   = (const float*)d_in[1];
    const float* W_ih = (const float*)d_in[2];
    const float* b_ih = (const float*)d_in[3];
    const float* W_hh = (const float*)d_in[4];
    const float* b_hh = (const float*)d_in[5];
    float* out = (float*)d_out;

    init_kernel<<<(BB * HH + 255) / 256, 256>>>(h0);

    dim3 g1(HH / 128, (BB * TT) / 128);
    gemm_xw_mma<<<g1, 256>>>(x, W_ih, b_ih, out);

    const int smem_bytes = (48 * 1024) * 4 + 4 * 528 * 4;  // 205056 B
    cudaFuncSetAttribute(rnn_scan_mma,
                         cudaFuncAttributeMaxDynamicSharedMemorySize, smem_bytes);
    rnn_scan_mma<<<NB_CTAS, RNN_THREADS, smem_bytes>>>(W_hh, b_hh, out);
}